// round 14
// baseline (speedup 1.0000x reference)
#include <cuda_runtime.h>
#include <stdint.h>
#include <stddef.h>

// Problem constants
#define BB 8
#define CC 64
#define MM 4
#define NN 400
#define TT 24
#define QQ 8
#define PP (MM*NN*TT)        // 38400 columns per batch
#define BNM (BB*NN*MM)       // 12800
#define MASK_NUM 1280        // int(12800*0.1)

typedef unsigned long long ull;

// -------- device scratch (no allocations allowed) --------
__device__ float g_w[BNM];
__device__ float g_levels[25600];
__device__ float g_scans[25600];
__device__ int   g_midx[MASK_NUM];
__device__ float g_Tp[CC*TT];
__device__ float g_Sp[CC*NN];
__device__ float g_Mp[CC*MM];       // includes proj_b folded in

// ============================================================
// packed f32x2 helpers (sm_100+) — R6-proven GEMM primitives
// ============================================================
__device__ __forceinline__ void ffma2(ull& d, ull a, ull b) {
    asm("fma.rn.f32x2 %0, %1, %2, %0;" : "+l"(d) : "l"(a), "l"(b));
}
__device__ __forceinline__ ull dup2(float x) {
    ull r; asm("mov.b64 %0, {%1,%1};" : "=l"(r) : "f"(x)); return r;
}
__device__ __forceinline__ float2 u2f(ull v) {
    float2 r; asm("mov.b64 {%0,%1}, %2;" : "=f"(r.x), "=f"(r.y) : "l"(v)); return r;
}

// ============================================================
// XLA:CPU exp (Cephes pexp, UNFUSED mul+add) — bit-frozen
// ============================================================
__device__ __forceinline__ float xla_exp(float input) {
    float x = fminf(input, 88.3762626647950f);
    x = fmaxf(x, -88.3762626647949f);
    float fx = __fadd_rn(__fmul_rn(x, 1.44269504088896341f), 0.5f);
    fx = floorf(fx);
    float tmp = __fmul_rn(fx, 0.693359375f);
    float z   = __fmul_rn(fx, -2.12194440e-4f);
    x = __fsub_rn(x, tmp);
    x = __fsub_rn(x, z);
    z = __fmul_rn(x, x);
    float y = 1.9875691500E-4f;
    y = __fadd_rn(__fmul_rn(y, x), 1.3981999507E-3f);
    y = __fadd_rn(__fmul_rn(y, x), 8.3334519073E-3f);
    y = __fadd_rn(__fmul_rn(y, x), 4.1665795894E-2f);
    y = __fadd_rn(__fmul_rn(y, x), 1.6666665459E-1f);
    y = __fadd_rn(__fmul_rn(y, x), 5.0000001201E-1f);
    y = __fadd_rn(__fmul_rn(y, z), x);
    y = __fadd_rn(y, 1.0f);
    int emm0 = (int)fx;
    emm0 = (emm0 + 0x7f) << 23;
    return __fmul_rn(y, __int_as_float(emm0));
}

// ============================================================
// threefry2x32-20, key = PRNGKey(42) = (0, 42) — bit-frozen
// ============================================================
__device__ __forceinline__ uint32_t rotl32(uint32_t x, int r) {
    return (x << r) | (x >> (32 - r));
}
__device__ void threefry2x32(uint32_t c0, uint32_t c1, uint32_t& o0, uint32_t& o1) {
    const uint32_t k0 = 0u, k1 = 42u;
    uint32_t ks[3] = {k0, k1, 0x1BD11BDAu ^ k0 ^ k1};
    uint32_t x0 = c0 + ks[0];
    uint32_t x1 = c1 + ks[1];
    const int rotA[4] = {13,15,26,6};
    const int rotB[4] = {17,29,16,24};
#pragma unroll
    for (int i = 0; i < 5; i++) {
#pragma unroll
        for (int j = 0; j < 4; j++) {
            int r = (i & 1) ? rotB[j] : rotA[j];
            x0 += x1;
            x1 = rotl32(x1, r);
            x1 ^= x0;
        }
        x0 += ks[(i + 1) % 3];
        x1 += ks[(i + 2) % 3] + (uint32_t)(i + 1);
    }
    o0 = x0; o1 = x1;
}

// ============================================================
// k_pre: blocks 0..199 -> sim/w; blocks 200..306 -> Tp/Sp/Mp  (bit-frozen ops)
// ============================================================
__global__ void __launch_bounds__(256) k_pre(
    const float* __restrict__ rep,
    const float* __restrict__ att_w,
    const float* __restrict__ att_b,
    const float* __restrict__ temb,
    const float* __restrict__ semb,
    const float* __restrict__ memb,
    const float* __restrict__ proj_w,
    const float* __restrict__ proj_b)
{
    const int bid = blockIdx.x;
    const int tid = threadIdx.x;

    if (bid >= 200) {
        const int idx = (bid - 200) * 256 + tid;
        const int total = CC * (TT + NN + MM);
        if (idx >= total) return;
        const int o = idx / (TT + NN + MM);
        const int j = idx % (TT + NN + MM);
        const float* w2 = proj_w + o*2*CC + CC;
        float acc = 0.f;
        if (j < TT) {
#pragma unroll 8
            for (int c = 0; c < CC; c++) acc = fmaf(w2[c], temb[c*TT + j], acc);
            g_Tp[o*TT + j] = acc;
        } else if (j < TT + NN) {
            const int n = j - TT;
#pragma unroll 8
            for (int c = 0; c < CC; c++) acc = fmaf(w2[c], semb[c*NN + n], acc);
            g_Sp[o*NN + n] = acc;
        } else {
            const int m = j - TT - NN;
#pragma unroll 8
            for (int c = 0; c < CC; c++) acc = fmaf(w2[c], memb[c*MM + m], acc);
            g_Mp[o*MM + m] = acc + proj_b[o];
        }
        return;
    }

    __shared__ float tile[CC*MM][17];
    __shared__ float aw[QQ*CC];
    __shared__ float pm_s[QQ][16][4];
    const int b  = bid / 25;
    const int n0 = (bid % 25) * 16;

    for (int i = tid; i < QQ*CC; i += 256) aw[i] = att_w[i];
    const float* repb = rep + (size_t)b * CC * MM * NN + n0;
#pragma unroll
    for (int it = 0; it < 16; it++) {          // 16 independent LDGs in flight
        int idx = it*256 + tid;
        int e = idx >> 4, j = idx & 15;
        tile[e][j] = repb[(size_t)e * NN + j];
    }
    __syncthreads();

    if (tid < 128) {
        const int q = tid >> 4, j = tid & 15;
        float A[4];
#pragma unroll
        for (int m = 0; m < 4; m++) {
            float acc = 0.f;
#pragma unroll 8
            for (int c = 0; c < CC; c++)
                acc = fmaf(tile[c*4 + m][j], aw[q*CC + c], acc);
            A[m] = __fadd_rn(acc, att_b[q]);
        }
        float mx = fmaxf(fmaxf(fmaxf(A[0], A[1]), A[2]), A[3]);
        float e[4];
#pragma unroll
        for (int m = 0; m < 4; m++) e[m] = xla_exp(__fsub_rn(A[m], mx));
        float s = __fadd_rn(__fadd_rn(__fadd_rn(e[0], e[1]), e[2]), e[3]);
#pragma unroll
        for (int m = 0; m < 4; m++) pm_s[q][j][m] = __fdiv_rn(e[m], s);
    }
    __syncthreads();

    if (tid < 64) {
        const int j = tid >> 2, m = tid & 3;
        float sumq = 0.f;
#pragma unroll
        for (int q = 0; q < 8; q++) sumq = __fadd_rn(sumq, pm_s[q][j][m]);
        float sim = __fmul_rn(sumq, 0.125f);
        g_w[(b*NN + n0 + j)*MM + m] = __fsub_rn(1.0f, sim);
    }
}

// ============================================================
// mask pipeline (block 0 of merged kernel, 256 threads)
// EXACT R6 version (proven 122.9us / 2.070723e-07) — register-light.
// ============================================================
__device__ void mask_work() {
    const int tid = threadIdx.x;
    __shared__ float S_sh;
    __shared__ float lane_sums[4];
    const int sizes[14] = {12800,6400,3200,1600,800,400,200,100,50,25,12,6,3,1};
    int offs[14];
    { int o = 0; for (int k = 0; k < 14; k++) { offs[k] = o; o += sizes[k]; } }

    volatile float* lv = g_levels;
    volatile float* sc = g_scans;

    // ---- S = sum(w): XLA:CPU EmitVectorizedReduce, NEON 4-lane ----
    if (tid < 4) {
        float a = 0.f;
#pragma unroll 8
        for (int j = 0; j < BNM/4; j++)
            a = __fadd_rn(a, g_w[4*j + tid]);
        lane_sums[tid] = a;
    }
    __syncthreads();
    if (tid == 0) {
        float lo = __fadd_rn(lane_sums[0], lane_sums[2]);
        float hi = __fadd_rn(lane_sums[1], lane_sums[3]);
        S_sh = __fadd_rn(lo, hi);
    }
    __syncthreads();
    const float S = S_sh;

    // ---- level 0: p = w / S ----
    for (int i = tid; i < BNM; i += 256) lv[i] = __fdiv_rn(g_w[i], S);
    __syncthreads();

    // ---- down-sweep ----
    for (int k = 0; k < 13; k++) {
        const int so = offs[k], dofs = offs[k+1];
        const int nk1 = sizes[k+1];
        for (int i = tid; i < nk1; i += 256) {
            float a = lv[so + 2*i];
            float b2 = lv[so + 2*i + 1];
            lv[dofs + i] = __fadd_rn(a, b2);
        }
        __syncthreads();
    }
    // ---- up-sweep: jax associative_scan interleave ----
    if (tid == 0) sc[offs[13]] = lv[offs[13]];
    __syncthreads();
    for (int k = 12; k >= 0; k--) {
        const int lo_ = offs[k], ho = offs[k+1];
        const int nk = sizes[k], nk1 = sizes[k+1];
        if (tid == 0) sc[lo_] = lv[lo_];
        for (int i = tid; i < nk1; i += 256) {
            float sv = sc[ho + i];
            sc[lo_ + 2*i + 1] = sv;
            if (2*i + 2 < nk) sc[lo_ + 2*i + 2] = __fadd_rn(sv, lv[lo_ + 2*i + 2]);
        }
        __syncthreads();
    }
    const float plast = sc[BNM - 1];

    // ---- sample 1280 indices (jax searchsorted method='scan') ----
    for (int k = tid; k < MASK_NUM; k += 256) {
        uint32_t o0, o1;
        threefry2x32(0u, (uint32_t)k, o0, o1);   // partitionable mode
        uint32_t bits = o0 ^ o1;
        float u = __fsub_rn(__uint_as_float((bits >> 9) | 0x3f800000u), 1.0f);
        float r = __fmul_rn(plast, __fsub_rn(1.0f, u));
        int low = 0, high = BNM;
#pragma unroll
        for (int it = 0; it < 14; it++) {        // ceil(log2(12801)) = 14
            int mid = (low + high) >> 1;
            bool go_left = (r <= g_scans[mid]);
            if (go_left) high = mid; else low = mid;
        }
        g_midx[k] = high;
    }
}

// ============================================================
// Merged kernel: block 0 = mask pipeline; blocks 1..2400 = GEMM
// R6 GEMM with smem-crossbar relief:
//   - Wsh row stride 68 (16B-aligned rows, 17.4KB)
//   - W staged conflict-free (o innermost per warp)
//   - W inner loads as 2x LDS.128 (ulonglong2)
// static smem = 17.4 + 16 KB = 33.4KB (proven-fast class)
// ============================================================
__global__ void __launch_bounds__(256) k_merged(const float* __restrict__ x,
                                                const float* __restrict__ proj_w,
                                                float* __restrict__ out) {
    __shared__ __align__(16) float Wsh[CC][68];   // 272B rows: 16B-aligned
    __shared__ float4 Xsh[32][32];

    if (blockIdx.x == 0) { mask_work(); return; }

    const int g  = blockIdx.x - 1;
    const int b  = g / 300;
    const int p0 = (g % 300) * 128;
    const int tid = threadIdx.x;
    const int to = tid >> 5;
    const int tp = tid & 31;

    // W staging: o innermost -> conflict-free STS (global reads L2-hot)
#pragma unroll
    for (int it = 0; it < 16; it++) {
        int i = it*256 + tid;
        int c = i >> 6, o = i & 63;
        Wsh[c][o] = proj_w[o*2*CC + c];
    }

    ull acc[4][4];
#pragma unroll
    for (int a = 0; a < 4; a++)
#pragma unroll
        for (int j = 0; j < 4; j++) acc[a][j] = 0ull;

    const size_t xbase = (size_t)b * CC * PP + p0;

#pragma unroll
    for (int ch = 0; ch < 2; ch++) {
        __syncthreads();
#pragma unroll
        for (int it = 0; it < 4; it++) {
            int idx = it*256 + tid;
            int cc = idx >> 5, p4 = idx & 31;
            Xsh[cc][p4] = *(const float4*)(x + xbase + (size_t)(ch*32 + cc)*PP + p4*4);
        }
        __syncthreads();

#pragma unroll 8
        for (int cc = 0; cc < 32; cc++) {
            const int c = ch*32 + cc;
            float4 xv = Xsh[cc][tp];
            ull x0 = dup2(xv.x), x1 = dup2(xv.y), x2 = dup2(xv.z), x3 = dup2(xv.w);
            const ulonglong2* wr2 = (const ulonglong2*)&Wsh[c][to*8]; // 16B-aligned
            ulonglong2 wA = wr2[0];
            ulonglong2 wB = wr2[1];
            ull w0 = wA.x, w1 = wA.y, w2 = wB.x, w3 = wB.y;
            ffma2(acc[0][0], w0, x0); ffma2(acc[0][1], w0, x1);
            ffma2(acc[0][2], w0, x2); ffma2(acc[0][3], w0, x3);
            ffma2(acc[1][0], w1, x0); ffma2(acc[1][1], w1, x1);
            ffma2(acc[1][2], w1, x2); ffma2(acc[1][3], w1, x3);
            ffma2(acc[2][0], w2, x0); ffma2(acc[2][1], w2, x1);
            ffma2(acc[2][2], w2, x2); ffma2(acc[2][3], w2, x3);
            ffma2(acc[3][0], w3, x0); ffma2(acc[3][1], w3, x1);
            ffma2(acc[3][2], w3, x2); ffma2(acc[3][3], w3, x3);
        }
    }

    const int m = p0 / 9600;
    const int obase = to*8;
    float mpv[8];
#pragma unroll
    for (int oo = 0; oo < 8; oo++) mpv[oo] = g_Mp[(obase+oo)*MM + m];

    float res[8][4];
#pragma unroll
    for (int pj = 0; pj < 4; pj++) {
        int p = p0 + tp*4 + pj;
        int t = p % 24;
        int n = (p / 24) % 400;
#pragma unroll
        for (int op = 0; op < 4; op++) {
            float2 a = u2f(acc[op][pj]);
            int o0 = obase + 2*op;
            float v0 = a.x + g_Tp[o0*TT + t]     + g_Sp[o0*NN + n]     + mpv[2*op];
            float v1 = a.y + g_Tp[(o0+1)*TT + t] + g_Sp[(o0+1)*NN + n] + mpv[2*op+1];
            res[2*op][pj]   = fmaxf(v0, 0.0f);
            res[2*op+1][pj] = fmaxf(v1, 0.0f);
        }
    }
#pragma unroll
    for (int oo = 0; oo < 8; oo++) {
        float4 v = make_float4(res[oo][0], res[oo][1], res[oo][2], res[oo][3]);
        *(float4*)(out + (size_t)(b*CC + obase + oo)*PP + p0 + tp*4) = v;
    }
}

// ============================================================
// k_fix: overwrite the 1280 masked (b,n,m) slices with relu(emb only)
// ============================================================
__global__ void __launch_bounds__(256) k_fix(float* __restrict__ out) {
    const int idx = g_midx[blockIdx.x];
    const int b = idx / (NN*MM);
    const int rr = idx % (NN*MM);
    const int n = rr >> 2;
    const int m = rr & 3;
    const int tid = threadIdx.x;
#pragma unroll
    for (int j = 0; j < 6; j++) {
        int i = j*256 + tid;
        int o = i / 24;
        int t = i % 24;
        float v = g_Tp[o*TT + t] + g_Sp[o*NN + n] + g_Mp[o*MM + m];
        out[((size_t)(b*CC + o)*MM + m)*NN*TT + n*TT + t] = fmaxf(v, 0.0f);
    }
}

// ============================================================
extern "C" void kernel_launch(void* const* d_in, const int* in_sizes, int n_in,
                              void* d_out, int out_size) {
    const float* x      = (const float*)d_in[0];
    const float* rep    = (const float*)d_in[1];
    const float* att_w  = (const float*)d_in[2];
    const float* att_b  = (const float*)d_in[3];
    const float* temb   = (const float*)d_in[4];
    const float* semb   = (const float*)d_in[5];
    const float* memb   = (const float*)d_in[6];
    const float* proj_w = (const float*)d_in[7];
    const float* proj_b = (const float*)d_in[8];
    float* out = (float*)d_out;

    k_pre<<<307, 256>>>(rep, att_w, att_b, temb, semb, memb, proj_w, proj_b);
    k_merged<<<2401, 256>>>(x, proj_w, out);
    k_fix<<<MASK_NUM, 256>>>(out);
}

// round 15
// speedup vs baseline: 1.0703x; 1.0703x over previous
#include <cuda_runtime.h>
#include <stdint.h>
#include <stddef.h>

// Problem constants
#define BB 8
#define CC 64
#define MM 4
#define NN 400
#define TT 24
#define QQ 8
#define PP (MM*NN*TT)        // 38400 columns per batch
#define BNM (BB*NN*MM)       // 12800
#define MASK_NUM 1280        // int(12800*0.1)

typedef unsigned long long ull;

// -------- device scratch (no allocations allowed) --------
__device__ float g_w[BNM];
__device__ float g_levels[25600];
__device__ float g_scans[25600];
__device__ int   g_midx[MASK_NUM];
__device__ float g_Tp[CC*TT];
__device__ float g_Sp[CC*NN];
__device__ float g_Mp[CC*MM];       // includes proj_b folded in

// ============================================================
// packed f32x2 helpers (sm_100+) — R6-proven GEMM primitives
// ============================================================
__device__ __forceinline__ void ffma2(ull& d, ull a, ull b) {
    asm("fma.rn.f32x2 %0, %1, %2, %0;" : "+l"(d) : "l"(a), "l"(b));
}
__device__ __forceinline__ ull dup2(float x) {
    ull r; asm("mov.b64 %0, {%1,%1};" : "=l"(r) : "f"(x)); return r;
}
__device__ __forceinline__ float2 u2f(ull v) {
    float2 r; asm("mov.b64 {%0,%1}, %2;" : "=f"(r.x), "=f"(r.y) : "l"(v)); return r;
}

// ============================================================
// XLA:CPU exp (Cephes pexp, UNFUSED mul+add) — bit-frozen
// ============================================================
__device__ __forceinline__ float xla_exp(float input) {
    float x = fminf(input, 88.3762626647950f);
    x = fmaxf(x, -88.3762626647949f);
    float fx = __fadd_rn(__fmul_rn(x, 1.44269504088896341f), 0.5f);
    fx = floorf(fx);
    float tmp = __fmul_rn(fx, 0.693359375f);
    float z   = __fmul_rn(fx, -2.12194440e-4f);
    x = __fsub_rn(x, tmp);
    x = __fsub_rn(x, z);
    z = __fmul_rn(x, x);
    float y = 1.9875691500E-4f;
    y = __fadd_rn(__fmul_rn(y, x), 1.3981999507E-3f);
    y = __fadd_rn(__fmul_rn(y, x), 8.3334519073E-3f);
    y = __fadd_rn(__fmul_rn(y, x), 4.1665795894E-2f);
    y = __fadd_rn(__fmul_rn(y, x), 1.6666665459E-1f);
    y = __fadd_rn(__fmul_rn(y, x), 5.0000001201E-1f);
    y = __fadd_rn(__fmul_rn(y, z), x);
    y = __fadd_rn(y, 1.0f);
    int emm0 = (int)fx;
    emm0 = (emm0 + 0x7f) << 23;
    return __fmul_rn(y, __int_as_float(emm0));
}

// ============================================================
// threefry2x32-20, key = PRNGKey(42) = (0, 42) — bit-frozen
// ============================================================
__device__ __forceinline__ uint32_t rotl32(uint32_t x, int r) {
    return (x << r) | (x >> (32 - r));
}
__device__ void threefry2x32(uint32_t c0, uint32_t c1, uint32_t& o0, uint32_t& o1) {
    const uint32_t k0 = 0u, k1 = 42u;
    uint32_t ks[3] = {k0, k1, 0x1BD11BDAu ^ k0 ^ k1};
    uint32_t x0 = c0 + ks[0];
    uint32_t x1 = c1 + ks[1];
    const int rotA[4] = {13,15,26,6};
    const int rotB[4] = {17,29,16,24};
#pragma unroll
    for (int i = 0; i < 5; i++) {
#pragma unroll
        for (int j = 0; j < 4; j++) {
            int r = (i & 1) ? rotB[j] : rotA[j];
            x0 += x1;
            x1 = rotl32(x1, r);
            x1 ^= x0;
        }
        x0 += ks[(i + 1) % 3];
        x1 += ks[(i + 2) % 3] + (uint32_t)(i + 1);
    }
    o0 = x0; o1 = x1;
}

// ============================================================
// k_pre: blocks 0..199 -> sim/w; blocks 200..306 -> Tp/Sp/Mp
// (bit-frozen ops; staging unroll proven in R14: 15.1 -> 11.5us)
// ============================================================
__global__ void __launch_bounds__(256) k_pre(
    const float* __restrict__ rep,
    const float* __restrict__ att_w,
    const float* __restrict__ att_b,
    const float* __restrict__ temb,
    const float* __restrict__ semb,
    const float* __restrict__ memb,
    const float* __restrict__ proj_w,
    const float* __restrict__ proj_b)
{
    const int bid = blockIdx.x;
    const int tid = threadIdx.x;

    if (bid >= 200) {
        const int idx = (bid - 200) * 256 + tid;
        const int total = CC * (TT + NN + MM);
        if (idx >= total) return;
        const int o = idx / (TT + NN + MM);
        const int j = idx % (TT + NN + MM);
        const float* w2 = proj_w + o*2*CC + CC;
        float acc = 0.f;
        if (j < TT) {
#pragma unroll 8
            for (int c = 0; c < CC; c++) acc = fmaf(w2[c], temb[c*TT + j], acc);
            g_Tp[o*TT + j] = acc;
        } else if (j < TT + NN) {
            const int n = j - TT;
#pragma unroll 8
            for (int c = 0; c < CC; c++) acc = fmaf(w2[c], semb[c*NN + n], acc);
            g_Sp[o*NN + n] = acc;
        } else {
            const int m = j - TT - NN;
#pragma unroll 8
            for (int c = 0; c < CC; c++) acc = fmaf(w2[c], memb[c*MM + m], acc);
            g_Mp[o*MM + m] = acc + proj_b[o];
        }
        return;
    }

    __shared__ float tile[CC*MM][17];
    __shared__ float aw[QQ*CC];
    __shared__ float pm_s[QQ][16][4];
    const int b  = bid / 25;
    const int n0 = (bid % 25) * 16;

    for (int i = tid; i < QQ*CC; i += 256) aw[i] = att_w[i];
    const float* repb = rep + (size_t)b * CC * MM * NN + n0;
#pragma unroll
    for (int it = 0; it < 16; it++) {          // 16 independent LDGs in flight
        int idx = it*256 + tid;
        int e = idx >> 4, j = idx & 15;
        tile[e][j] = repb[(size_t)e * NN + j];
    }
    __syncthreads();

    if (tid < 128) {
        const int q = tid >> 4, j = tid & 15;
        float A[4];
#pragma unroll
        for (int m = 0; m < 4; m++) {
            float acc = 0.f;
#pragma unroll 8
            for (int c = 0; c < CC; c++)
                acc = fmaf(tile[c*4 + m][j], aw[q*CC + c], acc);
            A[m] = __fadd_rn(acc, att_b[q]);
        }
        float mx = fmaxf(fmaxf(fmaxf(A[0], A[1]), A[2]), A[3]);
        float e[4];
#pragma unroll
        for (int m = 0; m < 4; m++) e[m] = xla_exp(__fsub_rn(A[m], mx));
        float s = __fadd_rn(__fadd_rn(__fadd_rn(e[0], e[1]), e[2]), e[3]);
#pragma unroll
        for (int m = 0; m < 4; m++) pm_s[q][j][m] = __fdiv_rn(e[m], s);
    }
    __syncthreads();

    if (tid < 64) {
        const int j = tid >> 2, m = tid & 3;
        float sumq = 0.f;
#pragma unroll
        for (int q = 0; q < 8; q++) sumq = __fadd_rn(sumq, pm_s[q][j][m]);
        float sim = __fmul_rn(sumq, 0.125f);
        g_w[(b*NN + n0 + j)*MM + m] = __fsub_rn(1.0f, sim);
    }
}

// ============================================================
// mask pipeline (block 0 of merged kernel, 256 threads)
// EXACT R6 version (proven 122.9us / 2.070723e-07) — register-light.
// ============================================================
__device__ void mask_work() {
    const int tid = threadIdx.x;
    __shared__ float S_sh;
    __shared__ float lane_sums[4];
    const int sizes[14] = {12800,6400,3200,1600,800,400,200,100,50,25,12,6,3,1};
    int offs[14];
    { int o = 0; for (int k = 0; k < 14; k++) { offs[k] = o; o += sizes[k]; } }

    volatile float* lv = g_levels;
    volatile float* sc = g_scans;

    // ---- S = sum(w): XLA:CPU EmitVectorizedReduce, NEON 4-lane ----
    if (tid < 4) {
        float a = 0.f;
#pragma unroll 8
        for (int j = 0; j < BNM/4; j++)
            a = __fadd_rn(a, g_w[4*j + tid]);
        lane_sums[tid] = a;
    }
    __syncthreads();
    if (tid == 0) {
        float lo = __fadd_rn(lane_sums[0], lane_sums[2]);
        float hi = __fadd_rn(lane_sums[1], lane_sums[3]);
        S_sh = __fadd_rn(lo, hi);
    }
    __syncthreads();
    const float S = S_sh;

    // ---- level 0: p = w / S ----
    for (int i = tid; i < BNM; i += 256) lv[i] = __fdiv_rn(g_w[i], S);
    __syncthreads();

    // ---- down-sweep ----
    for (int k = 0; k < 13; k++) {
        const int so = offs[k], dofs = offs[k+1];
        const int nk1 = sizes[k+1];
        for (int i = tid; i < nk1; i += 256) {
            float a = lv[so + 2*i];
            float b2 = lv[so + 2*i + 1];
            lv[dofs + i] = __fadd_rn(a, b2);
        }
        __syncthreads();
    }
    // ---- up-sweep: jax associative_scan interleave ----
    if (tid == 0) sc[offs[13]] = lv[offs[13]];
    __syncthreads();
    for (int k = 12; k >= 0; k--) {
        const int lo_ = offs[k], ho = offs[k+1];
        const int nk = sizes[k], nk1 = sizes[k+1];
        if (tid == 0) sc[lo_] = lv[lo_];
        for (int i = tid; i < nk1; i += 256) {
            float sv = sc[ho + i];
            sc[lo_ + 2*i + 1] = sv;
            if (2*i + 2 < nk) sc[lo_ + 2*i + 2] = __fadd_rn(sv, lv[lo_ + 2*i + 2]);
        }
        __syncthreads();
    }
    const float plast = sc[BNM - 1];

    // ---- sample 1280 indices (jax searchsorted method='scan') ----
    for (int k = tid; k < MASK_NUM; k += 256) {
        uint32_t o0, o1;
        threefry2x32(0u, (uint32_t)k, o0, o1);   // partitionable mode
        uint32_t bits = o0 ^ o1;
        float u = __fsub_rn(__uint_as_float((bits >> 9) | 0x3f800000u), 1.0f);
        float r = __fmul_rn(plast, __fsub_rn(1.0f, u));
        int low = 0, high = BNM;
#pragma unroll
        for (int it = 0; it < 14; it++) {        // ceil(log2(12801)) = 14
            int mid = (low + high) >> 1;
            bool go_left = (r <= g_scans[mid]);
            if (go_left) high = mid; else low = mid;
        }
        g_midx[k] = high;
    }
}

// ============================================================
// Merged kernel: block 0 = mask pipeline; blocks 1..2400 = GEMM
// R6 GEMM; only deltas vs the 122.9us champion:
//   - Wsh row stride 72 -> 68 (still 16B-aligned; STS conflict 8->4 way)
//   - W inner loads as 2x LDS.128 (ulonglong2; half the W wavefronts)
// W staging keeps R6's COALESCED global order (c innermost per lane).
// static smem = 17.4 + 16 KB = 33.4KB (proven-fast class)
// ============================================================
__global__ void __launch_bounds__(256) k_merged(const float* __restrict__ x,
                                                const float* __restrict__ proj_w,
                                                float* __restrict__ out) {
    __shared__ __align__(16) float Wsh[CC][68];   // 272B rows: 16B-aligned
    __shared__ float4 Xsh[32][32];

    if (blockIdx.x == 0) { mask_work(); return; }

    const int g  = blockIdx.x - 1;
    const int b  = g / 300;
    const int p0 = (g % 300) * 128;
    const int tid = threadIdx.x;
    const int to = tid >> 5;
    const int tp = tid & 31;

    // W staging: COALESCED global reads (R6 order), transposed STS
    for (int i = tid; i < CC*CC; i += 256) {
        int o = i >> 6, c = i & 63;
        Wsh[c][o] = proj_w[o*2*CC + c];
    }

    ull acc[4][4];
#pragma unroll
    for (int a = 0; a < 4; a++)
#pragma unroll
        for (int j = 0; j < 4; j++) acc[a][j] = 0ull;

    const size_t xbase = (size_t)b * CC * PP + p0;

#pragma unroll
    for (int ch = 0; ch < 2; ch++) {
        __syncthreads();
#pragma unroll
        for (int it = 0; it < 4; it++) {
            int idx = it*256 + tid;
            int cc = idx >> 5, p4 = idx & 31;
            Xsh[cc][p4] = *(const float4*)(x + xbase + (size_t)(ch*32 + cc)*PP + p4*4);
        }
        __syncthreads();

#pragma unroll 8
        for (int cc = 0; cc < 32; cc++) {
            const int c = ch*32 + cc;
            float4 xv = Xsh[cc][tp];
            ull x0 = dup2(xv.x), x1 = dup2(xv.y), x2 = dup2(xv.z), x3 = dup2(xv.w);
            const ulonglong2* wr2 = (const ulonglong2*)&Wsh[c][to*8]; // 16B-aligned
            ulonglong2 wA = wr2[0];
            ulonglong2 wB = wr2[1];
            ull w0 = wA.x, w1 = wA.y, w2 = wB.x, w3 = wB.y;
            ffma2(acc[0][0], w0, x0); ffma2(acc[0][1], w0, x1);
            ffma2(acc[0][2], w0, x2); ffma2(acc[0][3], w0, x3);
            ffma2(acc[1][0], w1, x0); ffma2(acc[1][1], w1, x1);
            ffma2(acc[1][2], w1, x2); ffma2(acc[1][3], w1, x3);
            ffma2(acc[2][0], w2, x0); ffma2(acc[2][1], w2, x1);
            ffma2(acc[2][2], w2, x2); ffma2(acc[2][3], w2, x3);
            ffma2(acc[3][0], w3, x0); ffma2(acc[3][1], w3, x1);
            ffma2(acc[3][2], w3, x2); ffma2(acc[3][3], w3, x3);
        }
    }

    const int m = p0 / 9600;
    const int obase = to*8;
    float mpv[8];
#pragma unroll
    for (int oo = 0; oo < 8; oo++) mpv[oo] = g_Mp[(obase+oo)*MM + m];

    float res[8][4];
#pragma unroll
    for (int pj = 0; pj < 4; pj++) {
        int p = p0 + tp*4 + pj;
        int t = p % 24;
        int n = (p / 24) % 400;
#pragma unroll
        for (int op = 0; op < 4; op++) {
            float2 a = u2f(acc[op][pj]);
            int o0 = obase + 2*op;
            float v0 = a.x + g_Tp[o0*TT + t]     + g_Sp[o0*NN + n]     + mpv[2*op];
            float v1 = a.y + g_Tp[(o0+1)*TT + t] + g_Sp[(o0+1)*NN + n] + mpv[2*op+1];
            res[2*op][pj]   = fmaxf(v0, 0.0f);
            res[2*op+1][pj] = fmaxf(v1, 0.0f);
        }
    }
#pragma unroll
    for (int oo = 0; oo < 8; oo++) {
        float4 v = make_float4(res[oo][0], res[oo][1], res[oo][2], res[oo][3]);
        *(float4*)(out + (size_t)(b*CC + obase + oo)*PP + p0 + tp*4) = v;
    }
}

// ============================================================
// k_fix: overwrite the 1280 masked (b,n,m) slices with relu(emb only)
// ============================================================
__global__ void __launch_bounds__(256) k_fix(float* __restrict__ out) {
    const int idx = g_midx[blockIdx.x];
    const int b = idx / (NN*MM);
    const int rr = idx % (NN*MM);
    const int n = rr >> 2;
    const int m = rr & 3;
    const int tid = threadIdx.x;
#pragma unroll
    for (int j = 0; j < 6; j++) {
        int i = j*256 + tid;
        int o = i / 24;
        int t = i % 24;
        float v = g_Tp[o*TT + t] + g_Sp[o*NN + n] + g_Mp[o*MM + m];
        out[((size_t)(b*CC + o)*MM + m)*NN*TT + n*TT + t] = fmaxf(v, 0.0f);
    }
}

// ============================================================
extern "C" void kernel_launch(void* const* d_in, const int* in_sizes, int n_in,
                              void* d_out, int out_size) {
    const float* x      = (const float*)d_in[0];
    const float* rep    = (const float*)d_in[1];
    const float* att_w  = (const float*)d_in[2];
    const float* att_b  = (const float*)d_in[3];
    const float* temb   = (const float*)d_in[4];
    const float* semb   = (const float*)d_in[5];
    const float* memb   = (const float*)d_in[6];
    const float* proj_w = (const float*)d_in[7];
    const float* proj_b = (const float*)d_in[8];
    float* out = (float*)d_out;

    k_pre<<<307, 256>>>(rep, att_w, att_b, temb, semb, memb, proj_w, proj_b);
    k_merged<<<2401, 256>>>(x, proj_w, out);
    k_fix<<<MASK_NUM, 256>>>(out);
}

// round 16
// speedup vs baseline: 1.1304x; 1.0562x over previous
#include <cuda_runtime.h>
#include <stdint.h>
#include <stddef.h>

// Problem constants
#define BB 8
#define CC 64
#define MM 4
#define NN 400
#define TT 24
#define QQ 8
#define PP (MM*NN*TT)        // 38400 columns per batch
#define BNM (BB*NN*MM)       // 12800
#define MASK_NUM 1280        // int(12800*0.1)

typedef unsigned long long ull;

// -------- device scratch (no allocations allowed) --------
__device__ float g_w[BNM];
__device__ float g_levels[25600];
__device__ float g_scans[25600];
__device__ int   g_midx[MASK_NUM];
__device__ float g_Tp[CC*TT];
__device__ float g_Sp[CC*NN];
__device__ float g_Mp[CC*MM];       // includes proj_b folded in

// ============================================================
// packed f32x2 helpers (sm_100+) — R6-proven GEMM primitives
// ============================================================
__device__ __forceinline__ void ffma2(ull& d, ull a, ull b) {
    asm("fma.rn.f32x2 %0, %1, %2, %0;" : "+l"(d) : "l"(a), "l"(b));
}
__device__ __forceinline__ ull dup2(float x) {
    ull r; asm("mov.b64 %0, {%1,%1};" : "=l"(r) : "f"(x)); return r;
}
__device__ __forceinline__ float2 u2f(ull v) {
    float2 r; asm("mov.b64 {%0,%1}, %2;" : "=f"(r.x), "=f"(r.y) : "l"(v)); return r;
}

// ============================================================
// XLA:CPU exp (Cephes pexp, UNFUSED mul+add) — bit-frozen
// ============================================================
__device__ __forceinline__ float xla_exp(float input) {
    float x = fminf(input, 88.3762626647950f);
    x = fmaxf(x, -88.3762626647949f);
    float fx = __fadd_rn(__fmul_rn(x, 1.44269504088896341f), 0.5f);
    fx = floorf(fx);
    float tmp = __fmul_rn(fx, 0.693359375f);
    float z   = __fmul_rn(fx, -2.12194440e-4f);
    x = __fsub_rn(x, tmp);
    x = __fsub_rn(x, z);
    z = __fmul_rn(x, x);
    float y = 1.9875691500E-4f;
    y = __fadd_rn(__fmul_rn(y, x), 1.3981999507E-3f);
    y = __fadd_rn(__fmul_rn(y, x), 8.3334519073E-3f);
    y = __fadd_rn(__fmul_rn(y, x), 4.1665795894E-2f);
    y = __fadd_rn(__fmul_rn(y, x), 1.6666665459E-1f);
    y = __fadd_rn(__fmul_rn(y, x), 5.0000001201E-1f);
    y = __fadd_rn(__fmul_rn(y, z), x);
    y = __fadd_rn(y, 1.0f);
    int emm0 = (int)fx;
    emm0 = (emm0 + 0x7f) << 23;
    return __fmul_rn(y, __int_as_float(emm0));
}

// ============================================================
// threefry2x32-20, key = PRNGKey(42) = (0, 42) — bit-frozen
// ============================================================
__device__ __forceinline__ uint32_t rotl32(uint32_t x, int r) {
    return (x << r) | (x >> (32 - r));
}
__device__ void threefry2x32(uint32_t c0, uint32_t c1, uint32_t& o0, uint32_t& o1) {
    const uint32_t k0 = 0u, k1 = 42u;
    uint32_t ks[3] = {k0, k1, 0x1BD11BDAu ^ k0 ^ k1};
    uint32_t x0 = c0 + ks[0];
    uint32_t x1 = c1 + ks[1];
    const int rotA[4] = {13,15,26,6};
    const int rotB[4] = {17,29,16,24};
#pragma unroll
    for (int i = 0; i < 5; i++) {
#pragma unroll
        for (int j = 0; j < 4; j++) {
            int r = (i & 1) ? rotB[j] : rotA[j];
            x0 += x1;
            x1 = rotl32(x1, r);
            x1 ^= x0;
        }
        x0 += ks[(i + 1) % 3];
        x1 += ks[(i + 2) % 3] + (uint32_t)(i + 1);
    }
    o0 = x0; o1 = x1;
}

// ============================================================
// k_pre: blocks 0..199 -> sim/w; blocks 200..306 -> Tp/Sp/Mp
// (bit-frozen ops; staging unroll proven in R14/R15: 15.1 -> 11.5us,
//  fingerprint unchanged)
// ============================================================
__global__ void __launch_bounds__(256) k_pre(
    const float* __restrict__ rep,
    const float* __restrict__ att_w,
    const float* __restrict__ att_b,
    const float* __restrict__ temb,
    const float* __restrict__ semb,
    const float* __restrict__ memb,
    const float* __restrict__ proj_w,
    const float* __restrict__ proj_b)
{
    const int bid = blockIdx.x;
    const int tid = threadIdx.x;

    if (bid >= 200) {
        const int idx = (bid - 200) * 256 + tid;
        const int total = CC * (TT + NN + MM);
        if (idx >= total) return;
        const int o = idx / (TT + NN + MM);
        const int j = idx % (TT + NN + MM);
        const float* w2 = proj_w + o*2*CC + CC;
        float acc = 0.f;
        if (j < TT) {
#pragma unroll 8
            for (int c = 0; c < CC; c++) acc = fmaf(w2[c], temb[c*TT + j], acc);
            g_Tp[o*TT + j] = acc;
        } else if (j < TT + NN) {
            const int n = j - TT;
#pragma unroll 8
            for (int c = 0; c < CC; c++) acc = fmaf(w2[c], semb[c*NN + n], acc);
            g_Sp[o*NN + n] = acc;
        } else {
            const int m = j - TT - NN;
#pragma unroll 8
            for (int c = 0; c < CC; c++) acc = fmaf(w2[c], memb[c*MM + m], acc);
            g_Mp[o*MM + m] = acc + proj_b[o];
        }
        return;
    }

    __shared__ float tile[CC*MM][17];
    __shared__ float aw[QQ*CC];
    __shared__ float pm_s[QQ][16][4];
    const int b  = bid / 25;
    const int n0 = (bid % 25) * 16;

    for (int i = tid; i < QQ*CC; i += 256) aw[i] = att_w[i];
    const float* repb = rep + (size_t)b * CC * MM * NN + n0;
#pragma unroll
    for (int it = 0; it < 16; it++) {          // 16 independent LDGs in flight
        int idx = it*256 + tid;
        int e = idx >> 4, j = idx & 15;
        tile[e][j] = repb[(size_t)e * NN + j];
    }
    __syncthreads();

    if (tid < 128) {
        const int q = tid >> 4, j = tid & 15;
        float A[4];
#pragma unroll
        for (int m = 0; m < 4; m++) {
            float acc = 0.f;
#pragma unroll 8
            for (int c = 0; c < CC; c++)
                acc = fmaf(tile[c*4 + m][j], aw[q*CC + c], acc);
            A[m] = __fadd_rn(acc, att_b[q]);
        }
        float mx = fmaxf(fmaxf(fmaxf(A[0], A[1]), A[2]), A[3]);
        float e[4];
#pragma unroll
        for (int m = 0; m < 4; m++) e[m] = xla_exp(__fsub_rn(A[m], mx));
        float s = __fadd_rn(__fadd_rn(__fadd_rn(e[0], e[1]), e[2]), e[3]);
#pragma unroll
        for (int m = 0; m < 4; m++) pm_s[q][j][m] = __fdiv_rn(e[m], s);
    }
    __syncthreads();

    if (tid < 64) {
        const int j = tid >> 2, m = tid & 3;
        float sumq = 0.f;
#pragma unroll
        for (int q = 0; q < 8; q++) sumq = __fadd_rn(sumq, pm_s[q][j][m]);
        float sim = __fmul_rn(sumq, 0.125f);
        g_w[(b*NN + n0 + j)*MM + m] = __fsub_rn(1.0f, sim);
    }
}

// ============================================================
// mask pipeline (block 0 of merged kernel, 256 threads)
// EXACT R6 version (proven 122.9us / 2.070723e-07)
// ============================================================
__device__ void mask_work() {
    const int tid = threadIdx.x;
    __shared__ float S_sh;
    __shared__ float lane_sums[4];
    const int sizes[14] = {12800,6400,3200,1600,800,400,200,100,50,25,12,6,3,1};
    int offs[14];
    { int o = 0; for (int k = 0; k < 14; k++) { offs[k] = o; o += sizes[k]; } }

    volatile float* lv = g_levels;
    volatile float* sc = g_scans;

    // ---- S = sum(w): XLA:CPU EmitVectorizedReduce, NEON 4-lane ----
    if (tid < 4) {
        float a = 0.f;
#pragma unroll 8
        for (int j = 0; j < BNM/4; j++)
            a = __fadd_rn(a, g_w[4*j + tid]);
        lane_sums[tid] = a;
    }
    __syncthreads();
    if (tid == 0) {
        float lo = __fadd_rn(lane_sums[0], lane_sums[2]);
        float hi = __fadd_rn(lane_sums[1], lane_sums[3]);
        S_sh = __fadd_rn(lo, hi);
    }
    __syncthreads();
    const float S = S_sh;

    // ---- level 0: p = w / S ----
    for (int i = tid; i < BNM; i += 256) lv[i] = __fdiv_rn(g_w[i], S);
    __syncthreads();

    // ---- down-sweep ----
    for (int k = 0; k < 13; k++) {
        const int so = offs[k], dofs = offs[k+1];
        const int nk1 = sizes[k+1];
        for (int i = tid; i < nk1; i += 256) {
            float a = lv[so + 2*i];
            float b2 = lv[so + 2*i + 1];
            lv[dofs + i] = __fadd_rn(a, b2);
        }
        __syncthreads();
    }
    // ---- up-sweep: jax associative_scan interleave ----
    if (tid == 0) sc[offs[13]] = lv[offs[13]];
    __syncthreads();
    for (int k = 12; k >= 0; k--) {
        const int lo_ = offs[k], ho = offs[k+1];
        const int nk = sizes[k], nk1 = sizes[k+1];
        if (tid == 0) sc[lo_] = lv[lo_];
        for (int i = tid; i < nk1; i += 256) {
            float sv = sc[ho + i];
            sc[lo_ + 2*i + 1] = sv;
            if (2*i + 2 < nk) sc[lo_ + 2*i + 2] = __fadd_rn(sv, lv[lo_ + 2*i + 2]);
        }
        __syncthreads();
    }
    const float plast = sc[BNM - 1];

    // ---- sample 1280 indices (jax searchsorted method='scan') ----
    for (int k = tid; k < MASK_NUM; k += 256) {
        uint32_t o0, o1;
        threefry2x32(0u, (uint32_t)k, o0, o1);   // partitionable mode
        uint32_t bits = o0 ^ o1;
        float u = __fsub_rn(__uint_as_float((bits >> 9) | 0x3f800000u), 1.0f);
        float r = __fmul_rn(plast, __fsub_rn(1.0f, u));
        int low = 0, high = BNM;
#pragma unroll
        for (int it = 0; it < 14; it++) {        // ceil(log2(12801)) = 14
            int mid = (low + high) >> 1;
            bool go_left = (r <= g_scans[mid]);
            if (go_left) high = mid; else low = mid;
        }
        g_midx[k] = high;
    }
}

// ============================================================
// Merged kernel: block 0 = mask pipeline; blocks 1..2400 = GEMM
// EXACT R6 GEMM (byte-identical to the 122.9us champion)
// ============================================================
__global__ void __launch_bounds__(256) k_merged(const float* __restrict__ x,
                                                const float* __restrict__ proj_w,
                                                float* __restrict__ out) {
    // row stride 72 floats = 288 B -> &Wsh[c][to*8] is always 16B-aligned
    __shared__ __align__(16) float Wsh[CC][72];
    __shared__ float4 Xsh[32][32];

    if (blockIdx.x == 0) { mask_work(); return; }

    const int g  = blockIdx.x - 1;
    const int b  = g / 300;
    const int p0 = (g % 300) * 128;
    const int tid = threadIdx.x;
    const int to = tid >> 5;
    const int tp = tid & 31;

    for (int i = tid; i < CC*CC; i += 256) {
        int o = i >> 6, c = i & 63;
        Wsh[c][o] = proj_w[o*2*CC + c];
    }

    ull acc[4][4];
#pragma unroll
    for (int a = 0; a < 4; a++)
#pragma unroll
        for (int j = 0; j < 4; j++) acc[a][j] = 0ull;

    const size_t xbase = (size_t)b * CC * PP + p0;

#pragma unroll
    for (int ch = 0; ch < 2; ch++) {
        __syncthreads();
#pragma unroll
        for (int it = 0; it < 4; it++) {
            int idx = it*256 + tid;
            int cc = idx >> 5, p4 = idx & 31;
            Xsh[cc][p4] = *(const float4*)(x + xbase + (size_t)(ch*32 + cc)*PP + p4*4);
        }
        __syncthreads();

#pragma unroll 8
        for (int cc = 0; cc < 32; cc++) {
            const int c = ch*32 + cc;
            float4 xv = Xsh[cc][tp];
            ull x0 = dup2(xv.x), x1 = dup2(xv.y), x2 = dup2(xv.z), x3 = dup2(xv.w);
            const ull* wr = (const ull*)&Wsh[c][to*8];  // 16B-aligned
            ull w0 = wr[0], w1 = wr[1], w2 = wr[2], w3 = wr[3];
            ffma2(acc[0][0], w0, x0); ffma2(acc[0][1], w0, x1);
            ffma2(acc[0][2], w0, x2); ffma2(acc[0][3], w0, x3);
            ffma2(acc[1][0], w1, x0); ffma2(acc[1][1], w1, x1);
            ffma2(acc[1][2], w1, x2); ffma2(acc[1][3], w1, x3);
            ffma2(acc[2][0], w2, x0); ffma2(acc[2][1], w2, x1);
            ffma2(acc[2][2], w2, x2); ffma2(acc[2][3], w2, x3);
            ffma2(acc[3][0], w3, x0); ffma2(acc[3][1], w3, x1);
            ffma2(acc[3][2], w3, x2); ffma2(acc[3][3], w3, x3);
        }
    }

    const int m = p0 / 9600;
    const int obase = to*8;
    float mpv[8];
#pragma unroll
    for (int oo = 0; oo < 8; oo++) mpv[oo] = g_Mp[(obase+oo)*MM + m];

    float res[8][4];
#pragma unroll
    for (int pj = 0; pj < 4; pj++) {
        int p = p0 + tp*4 + pj;
        int t = p % 24;
        int n = (p / 24) % 400;
#pragma unroll
        for (int op = 0; op < 4; op++) {
            float2 a = u2f(acc[op][pj]);
            int o0 = obase + 2*op;
            float v0 = a.x + g_Tp[o0*TT + t]     + g_Sp[o0*NN + n]     + mpv[2*op];
            float v1 = a.y + g_Tp[(o0+1)*TT + t] + g_Sp[(o0+1)*NN + n] + mpv[2*op+1];
            res[2*op][pj]   = fmaxf(v0, 0.0f);
            res[2*op+1][pj] = fmaxf(v1, 0.0f);
        }
    }
#pragma unroll
    for (int oo = 0; oo < 8; oo++) {
        float4 v = make_float4(res[oo][0], res[oo][1], res[oo][2], res[oo][3]);
        *(float4*)(out + (size_t)(b*CC + obase + oo)*PP + p0 + tp*4) = v;
    }
}

// ============================================================
// k_fix: overwrite the 1280 masked (b,n,m) slices with relu(emb only)
// ============================================================
__global__ void __launch_bounds__(256) k_fix(float* __restrict__ out) {
    const int idx = g_midx[blockIdx.x];
    const int b = idx / (NN*MM);
    const int rr = idx % (NN*MM);
    const int n = rr >> 2;
    const int m = rr & 3;
    const int tid = threadIdx.x;
#pragma unroll
    for (int j = 0; j < 6; j++) {
        int i = j*256 + tid;
        int o = i / 24;
        int t = i % 24;
        float v = g_Tp[o*TT + t] + g_Sp[o*NN + n] + g_Mp[o*MM + m];
        out[((size_t)(b*CC + o)*MM + m)*NN*TT + n*TT + t] = fmaxf(v, 0.0f);
    }
}

// ============================================================
extern "C" void kernel_launch(void* const* d_in, const int* in_sizes, int n_in,
                              void* d_out, int out_size) {
    const float* x      = (const float*)d_in[0];
    const float* rep    = (const float*)d_in[1];
    const float* att_w  = (const float*)d_in[2];
    const float* att_b  = (const float*)d_in[3];
    const float* temb   = (const float*)d_in[4];
    const float* semb   = (const float*)d_in[5];
    const float* memb   = (const float*)d_in[6];
    const float* proj_w = (const float*)d_in[7];
    const float* proj_b = (const float*)d_in[8];
    float* out = (float*)d_out;

    k_pre<<<307, 256>>>(rep, att_w, att_b, temb, semb, memb, proj_w, proj_b);
    k_merged<<<2401, 256>>>(x, proj_w, out);
    k_fix<<<MASK_NUM, 256>>>(out);
}

// round 17
// speedup vs baseline: 2.1951x; 1.9418x over previous
#include <cuda_runtime.h>
#include <stdint.h>
#include <stddef.h>

// Problem constants
#define BB 8
#define CC 64
#define MM 4
#define NN 400
#define TT 24
#define QQ 8
#define PP (MM*NN*TT)        // 38400 columns per batch
#define BNM (BB*NN*MM)       // 12800
#define MASK_NUM 1280        // int(12800*0.1)

typedef unsigned long long ull;

// -------- device scratch (no allocations allowed) --------
__device__ float g_w[BNM];
__device__ float g_levels[25600];
__device__ float g_scans[25600];
__device__ int   g_midx[MASK_NUM];
__device__ float g_Tp[CC*TT];
__device__ float g_Sp[CC*NN];
__device__ float g_Mp[CC*MM];       // includes proj_b folded in

// ============================================================
// packed f32x2 helpers (sm_100+) — R6-proven GEMM primitives
// ============================================================
__device__ __forceinline__ void ffma2(ull& d, ull a, ull b) {
    asm("fma.rn.f32x2 %0, %1, %2, %0;" : "+l"(d) : "l"(a), "l"(b));
}
__device__ __forceinline__ ull dup2(float x) {
    ull r; asm("mov.b64 %0, {%1,%1};" : "=l"(r) : "f"(x)); return r;
}
__device__ __forceinline__ float2 u2f(ull v) {
    float2 r; asm("mov.b64 {%0,%1}, %2;" : "=f"(r.x), "=f"(r.y) : "l"(v)); return r;
}

// ============================================================
// XLA:CPU exp (Cephes pexp, UNFUSED mul+add) — bit-frozen
// ============================================================
__device__ __forceinline__ float xla_exp(float input) {
    float x = fminf(input, 88.3762626647950f);
    x = fmaxf(x, -88.3762626647949f);
    float fx = __fadd_rn(__fmul_rn(x, 1.44269504088896341f), 0.5f);
    fx = floorf(fx);
    float tmp = __fmul_rn(fx, 0.693359375f);
    float z   = __fmul_rn(fx, -2.12194440e-4f);
    x = __fsub_rn(x, tmp);
    x = __fsub_rn(x, z);
    z = __fmul_rn(x, x);
    float y = 1.9875691500E-4f;
    y = __fadd_rn(__fmul_rn(y, x), 1.3981999507E-3f);
    y = __fadd_rn(__fmul_rn(y, x), 8.3334519073E-3f);
    y = __fadd_rn(__fmul_rn(y, x), 4.1665795894E-2f);
    y = __fadd_rn(__fmul_rn(y, x), 1.6666665459E-1f);
    y = __fadd_rn(__fmul_rn(y, x), 5.0000001201E-1f);
    y = __fadd_rn(__fmul_rn(y, z), x);
    y = __fadd_rn(y, 1.0f);
    int emm0 = (int)fx;
    emm0 = (emm0 + 0x7f) << 23;
    return __fmul_rn(y, __int_as_float(emm0));
}

// ============================================================
// threefry2x32-20, key = PRNGKey(42) = (0, 42) — bit-frozen
// ============================================================
__device__ __forceinline__ uint32_t rotl32(uint32_t x, int r) {
    return (x << r) | (x >> (32 - r));
}
__device__ void threefry2x32(uint32_t c0, uint32_t c1, uint32_t& o0, uint32_t& o1) {
    const uint32_t k0 = 0u, k1 = 42u;
    uint32_t ks[3] = {k0, k1, 0x1BD11BDAu ^ k0 ^ k1};
    uint32_t x0 = c0 + ks[0];
    uint32_t x1 = c1 + ks[1];
    const int rotA[4] = {13,15,26,6};
    const int rotB[4] = {17,29,16,24};
#pragma unroll
    for (int i = 0; i < 5; i++) {
#pragma unroll
        for (int j = 0; j < 4; j++) {
            int r = (i & 1) ? rotB[j] : rotA[j];
            x0 += x1;
            x1 = rotl32(x1, r);
            x1 ^= x0;
        }
        x0 += ks[(i + 1) % 3];
        x1 += ks[(i + 2) % 3] + (uint32_t)(i + 1);
    }
    o0 = x0; o1 = x1;
}

// ============================================================
// k_pre: blocks 0..199 -> sim/w; blocks 200..306 -> Tp/Sp/Mp
// (bit-frozen ops; staging unroll proven: 15.1 -> 11.5us, same fingerprint)
// ============================================================
__global__ void __launch_bounds__(256) k_pre(
    const float* __restrict__ rep,
    const float* __restrict__ att_w,
    const float* __restrict__ att_b,
    const float* __restrict__ temb,
    const float* __restrict__ semb,
    const float* __restrict__ memb,
    const float* __restrict__ proj_w,
    const float* __restrict__ proj_b)
{
    const int bid = blockIdx.x;
    const int tid = threadIdx.x;

    if (bid >= 200) {
        const int idx = (bid - 200) * 256 + tid;
        const int total = CC * (TT + NN + MM);
        if (idx >= total) return;
        const int o = idx / (TT + NN + MM);
        const int j = idx % (TT + NN + MM);
        const float* w2 = proj_w + o*2*CC + CC;
        float acc = 0.f;
        if (j < TT) {
#pragma unroll 8
            for (int c = 0; c < CC; c++) acc = fmaf(w2[c], temb[c*TT + j], acc);
            g_Tp[o*TT + j] = acc;
        } else if (j < TT + NN) {
            const int n = j - TT;
#pragma unroll 8
            for (int c = 0; c < CC; c++) acc = fmaf(w2[c], semb[c*NN + n], acc);
            g_Sp[o*NN + n] = acc;
        } else {
            const int m = j - TT - NN;
#pragma unroll 8
            for (int c = 0; c < CC; c++) acc = fmaf(w2[c], memb[c*MM + m], acc);
            g_Mp[o*MM + m] = acc + proj_b[o];
        }
        return;
    }

    __shared__ float tile[CC*MM][17];
    __shared__ float aw[QQ*CC];
    __shared__ float pm_s[QQ][16][4];
    const int b  = bid / 25;
    const int n0 = (bid % 25) * 16;

    for (int i = tid; i < QQ*CC; i += 256) aw[i] = att_w[i];
    const float* repb = rep + (size_t)b * CC * MM * NN + n0;
#pragma unroll
    for (int it = 0; it < 16; it++) {          // 16 independent LDGs in flight
        int idx = it*256 + tid;
        int e = idx >> 4, j = idx & 15;
        tile[e][j] = repb[(size_t)e * NN + j];
    }
    __syncthreads();

    if (tid < 128) {
        const int q = tid >> 4, j = tid & 15;
        float A[4];
#pragma unroll
        for (int m = 0; m < 4; m++) {
            float acc = 0.f;
#pragma unroll 8
            for (int c = 0; c < CC; c++)
                acc = fmaf(tile[c*4 + m][j], aw[q*CC + c], acc);
            A[m] = __fadd_rn(acc, att_b[q]);
        }
        float mx = fmaxf(fmaxf(fmaxf(A[0], A[1]), A[2]), A[3]);
        float e[4];
#pragma unroll
        for (int m = 0; m < 4; m++) e[m] = xla_exp(__fsub_rn(A[m], mx));
        float s = __fadd_rn(__fadd_rn(__fadd_rn(e[0], e[1]), e[2]), e[3]);
#pragma unroll
        for (int m = 0; m < 4; m++) pm_s[q][j][m] = __fdiv_rn(e[m], s);
    }
    __syncthreads();

    if (tid < 64) {
        const int j = tid >> 2, m = tid & 3;
        float sumq = 0.f;
#pragma unroll
        for (int q = 0; q < 8; q++) sumq = __fadd_rn(sumq, pm_s[q][j][m]);
        float sim = __fmul_rn(sumq, 0.125f);
        g_w[(b*NN + n0 + j)*MM + m] = __fsub_rn(1.0f, sim);
    }
}

// ============================================================
// mask pipeline (block 0 of merged kernel, 256 threads)
// R6 arithmetic bit-frozen. ONE change: the S-sum reads g_w through a
// two-half SMEM staging buffer (bit-copies; per-lane add sequence
// identical), removing the L2/DRAM-weather dependence that caused the
// 120 vs 220us bimodality across runs.
// ============================================================
__device__ void mask_work(float* stage) {
    const int tid = threadIdx.x;
    __shared__ float S_sh;
    __shared__ float lane_sums[4];
    const int sizes[14] = {12800,6400,3200,1600,800,400,200,100,50,25,12,6,3,1};
    int offs[14];
    { int o = 0; for (int k = 0; k < 14; k++) { offs[k] = o; o += sizes[k]; } }

    volatile float* lv = g_levels;
    volatile float* sc = g_scans;

    // ---- S = sum(w): NEON 4-lane, staged through smem in two halves ----
    // lane t sums w[4j+t] for j = 0..3199 in ascending order (bit-exact).
    float acc = 0.f;
#pragma unroll
    for (int h = 0; h < 2; h++) {
        __syncthreads();
        for (int i = tid; i < 6400; i += 256)
            stage[i] = g_w[h*6400 + i];       // coalesced bit-copy
        __syncthreads();
        if (tid < 4) {
#pragma unroll 8
            for (int j = 0; j < 1600; j++)
                acc = __fadd_rn(acc, stage[4*j + tid]);
        }
    }
    if (tid < 4) lane_sums[tid] = acc;
    __syncthreads();
    if (tid == 0) {
        float lo = __fadd_rn(lane_sums[0], lane_sums[2]);
        float hi = __fadd_rn(lane_sums[1], lane_sums[3]);
        S_sh = __fadd_rn(lo, hi);
    }
    __syncthreads();
    const float S = S_sh;

    // ---- level 0: p = w / S ----
    for (int i = tid; i < BNM; i += 256) lv[i] = __fdiv_rn(g_w[i], S);
    __syncthreads();

    // ---- down-sweep ----
    for (int k = 0; k < 13; k++) {
        const int so = offs[k], dofs = offs[k+1];
        const int nk1 = sizes[k+1];
        for (int i = tid; i < nk1; i += 256) {
            float a = lv[so + 2*i];
            float b2 = lv[so + 2*i + 1];
            lv[dofs + i] = __fadd_rn(a, b2);
        }
        __syncthreads();
    }
    // ---- up-sweep: jax associative_scan interleave ----
    if (tid == 0) sc[offs[13]] = lv[offs[13]];
    __syncthreads();
    for (int k = 12; k >= 0; k--) {
        const int lo_ = offs[k], ho = offs[k+1];
        const int nk = sizes[k], nk1 = sizes[k+1];
        if (tid == 0) sc[lo_] = lv[lo_];
        for (int i = tid; i < nk1; i += 256) {
            float sv = sc[ho + i];
            sc[lo_ + 2*i + 1] = sv;
            if (2*i + 2 < nk) sc[lo_ + 2*i + 2] = __fadd_rn(sv, lv[lo_ + 2*i + 2]);
        }
        __syncthreads();
    }
    const float plast = sc[BNM - 1];

    // ---- sample 1280 indices (jax searchsorted method='scan') ----
    for (int k = tid; k < MASK_NUM; k += 256) {
        uint32_t o0, o1;
        threefry2x32(0u, (uint32_t)k, o0, o1);   // partitionable mode
        uint32_t bits = o0 ^ o1;
        float u = __fsub_rn(__uint_as_float((bits >> 9) | 0x3f800000u), 1.0f);
        float r = __fmul_rn(plast, __fsub_rn(1.0f, u));
        int low = 0, high = BNM;
#pragma unroll
        for (int it = 0; it < 14; it++) {        // ceil(log2(12801)) = 14
            int mid = (low + high) >> 1;
            bool go_left = (r <= g_scans[mid]);
            if (go_left) high = mid; else low = mid;
        }
        g_midx[k] = high;
    }
}

// ============================================================
// Merged kernel: block 0 = mask pipeline; blocks 1..2400 = GEMM
// GEMM path byte-identical to the 122.9us champion; smem is a UNION so
// block 0's staging buffer reuses the GEMM arrays (same 34.8KB static).
// ============================================================
union SmemU {
    struct {
        float  Wsh[CC][72];     // row stride 288B -> 16B-aligned
        float4 Xsh[32][32];
    } g;
    float stage[6400];          // mask S-sum staging (25.6KB < 34.8KB)
};

__global__ void __launch_bounds__(256) k_merged(const float* __restrict__ x,
                                                const float* __restrict__ proj_w,
                                                float* __restrict__ out) {
    __shared__ __align__(16) SmemU smu;

    if (blockIdx.x == 0) { mask_work(smu.stage); return; }

    float  (*Wsh)[72] = smu.g.Wsh;
    float4 (*Xsh)[32] = smu.g.Xsh;

    const int g  = blockIdx.x - 1;
    const int b  = g / 300;
    const int p0 = (g % 300) * 128;
    const int tid = threadIdx.x;
    const int to = tid >> 5;
    const int tp = tid & 31;

    for (int i = tid; i < CC*CC; i += 256) {
        int o = i >> 6, c = i & 63;
        Wsh[c][o] = proj_w[o*2*CC + c];
    }

    ull acc[4][4];
#pragma unroll
    for (int a = 0; a < 4; a++)
#pragma unroll
        for (int j = 0; j < 4; j++) acc[a][j] = 0ull;

    const size_t xbase = (size_t)b * CC * PP + p0;

#pragma unroll
    for (int ch = 0; ch < 2; ch++) {
        __syncthreads();
#pragma unroll
        for (int it = 0; it < 4; it++) {
            int idx = it*256 + tid;
            int cc = idx >> 5, p4 = idx & 31;
            Xsh[cc][p4] = *(const float4*)(x + xbase + (size_t)(ch*32 + cc)*PP + p4*4);
        }
        __syncthreads();

#pragma unroll 8
        for (int cc = 0; cc < 32; cc++) {
            const int c = ch*32 + cc;
            float4 xv = Xsh[cc][tp];
            ull x0 = dup2(xv.x), x1 = dup2(xv.y), x2 = dup2(xv.z), x3 = dup2(xv.w);
            const ull* wr = (const ull*)&Wsh[c][to*8];  // 16B-aligned
            ull w0 = wr[0], w1 = wr[1], w2 = wr[2], w3 = wr[3];
            ffma2(acc[0][0], w0, x0); ffma2(acc[0][1], w0, x1);
            ffma2(acc[0][2], w0, x2); ffma2(acc[0][3], w0, x3);
            ffma2(acc[1][0], w1, x0); ffma2(acc[1][1], w1, x1);
            ffma2(acc[1][2], w1, x2); ffma2(acc[1][3], w1, x3);
            ffma2(acc[2][0], w2, x0); ffma2(acc[2][1], w2, x1);
            ffma2(acc[2][2], w2, x2); ffma2(acc[2][3], w2, x3);
            ffma2(acc[3][0], w3, x0); ffma2(acc[3][1], w3, x1);
            ffma2(acc[3][2], w3, x2); ffma2(acc[3][3], w3, x3);
        }
    }

    const int m = p0 / 9600;
    const int obase = to*8;
    float mpv[8];
#pragma unroll
    for (int oo = 0; oo < 8; oo++) mpv[oo] = g_Mp[(obase+oo)*MM + m];

    float res[8][4];
#pragma unroll
    for (int pj = 0; pj < 4; pj++) {
        int p = p0 + tp*4 + pj;
        int t = p % 24;
        int n = (p / 24) % 400;
#pragma unroll
        for (int op = 0; op < 4; op++) {
            float2 a = u2f(acc[op][pj]);
            int o0 = obase + 2*op;
            float v0 = a.x + g_Tp[o0*TT + t]     + g_Sp[o0*NN + n]     + mpv[2*op];
            float v1 = a.y + g_Tp[(o0+1)*TT + t] + g_Sp[(o0+1)*NN + n] + mpv[2*op+1];
            res[2*op][pj]   = fmaxf(v0, 0.0f);
            res[2*op+1][pj] = fmaxf(v1, 0.0f);
        }
    }
#pragma unroll
    for (int oo = 0; oo < 8; oo++) {
        float4 v = make_float4(res[oo][0], res[oo][1], res[oo][2], res[oo][3]);
        *(float4*)(out + (size_t)(b*CC + obase + oo)*PP + p0 + tp*4) = v;
    }
}

// ============================================================
// k_fix: overwrite the 1280 masked (b,n,m) slices with relu(emb only)
// ============================================================
__global__ void __launch_bounds__(256) k_fix(float* __restrict__ out) {
    const int idx = g_midx[blockIdx.x];
    const int b = idx / (NN*MM);
    const int rr = idx % (NN*MM);
    const int n = rr >> 2;
    const int m = rr & 3;
    const int tid = threadIdx.x;
#pragma unroll
    for (int j = 0; j < 6; j++) {
        int i = j*256 + tid;
        int o = i / 24;
        int t = i % 24;
        float v = g_Tp[o*TT + t] + g_Sp[o*NN + n] + g_Mp[o*MM + m];
        out[((size_t)(b*CC + o)*MM + m)*NN*TT + n*TT + t] = fmaxf(v, 0.0f);
    }
}

// ============================================================
extern "C" void kernel_launch(void* const* d_in, const int* in_sizes, int n_in,
                              void* d_out, int out_size) {
    const float* x      = (const float*)d_in[0];
    const float* rep    = (const float*)d_in[1];
    const float* att_w  = (const float*)d_in[2];
    const float* att_b  = (const float*)d_in[3];
    const float* temb   = (const float*)d_in[4];
    const float* semb   = (const float*)d_in[5];
    const float* memb   = (const float*)d_in[6];
    const float* proj_w = (const float*)d_in[7];
    const float* proj_b = (const float*)d_in[8];
    float* out = (float*)d_out;

    k_pre<<<307, 256>>>(rep, att_w, att_b, temb, semb, memb, proj_w, proj_b);
    k_merged<<<2401, 256>>>(x, proj_w, out);
    k_fix<<<MASK_NUM, 256>>>(out);
}